// round 16
// baseline (speedup 1.0000x reference)
#include <cuda_runtime.h>

#define Bq   16
#define Kq   32
#define Lq   1024
#define Dq   128
#define NEWL 48

#define NEG_INF __int_as_float(0xff800000)
#define NTHR   384
#define N_ALM  16384u      // almat blocks: 6,291,456 float4 / 384 (exact)

#define NSEG1  49          // 48 real segments + 1 trash slot (s == NEWL rows)
#define CPY    (NSEG1 * 32)     // float4 slots per warp copy = 1568
#define DSMEM  (4 * CPY * 16)   // 100,352 B dynamic smem

__device__ __forceinline__ int seg_of(float tv) {
    return (tv >= 0.f && tv < 48.f) ? (int)tv : NEWL;
}

// K1: pure almat. (B,K,L,48) one-hot, float4 stores, 32-bit indexing.
__global__ void __launch_bounds__(NTHR) almat_kernel(const float* __restrict__ et,
                                                     float* __restrict__ out_a) {
    unsigned g   = blockIdx.x * (unsigned)NTHR + threadIdx.x;   // exact cover
    unsigned row = g / 12u;               // (b,k,l) flat — u32 mul-high
    unsigned qq  = g - row * 12u;
    unsigned l   = row & (Lq - 1);
    unsigned b   = row >> 15;             // / (K*L), K*L = 2^15
    float tv = __ldg(&et[b * Lq + l]);
    int s = seg_of(tv);
    float4 v = make_float4(0.f, 0.f, 0.f, 0.f);
    int o = s - (int)(qq * 4u);
    if (o >= 0 && o < 4) (&v.x)[o] = 1.f;
    reinterpret_cast<float4*>(out_a)[g] = v;
}

// K2: STREAMING segmax. One block per (b,k), 128 threads (4 warps).
// h0 read SEQUENTIALLY (block covers rows in l order; warp w takes rows l%4==w).
// Each warp scatter-maxes into its PRIVATE smem copy (49x32 float4) — no races.
// 8 rows staged into registers per batch => 8 independent LDG.128 in flight.
// counts/tsum/msum computed in-block from et/npm (L2-hot); no prep, no scratch.
__global__ void __launch_bounds__(128) segmax_stream(const float* __restrict__ h0,
                                                     const float* __restrict__ et,
                                                     const float* __restrict__ npm,
                                                     float* __restrict__ o_h,
                                                     float* __restrict__ o_pm,
                                                     float* __restrict__ o_et) {
    extern __shared__ float4 acc[];               // 4 copies x 49 x 32 float4
    __shared__ unsigned char sseg[Lq];
    __shared__ int   scnt[NEWL + 1];
    __shared__ float stsum[NEWL];
    __shared__ float smsum[NEWL];

    const int bk = blockIdx.x;                    // 0..511
    const int b  = bk >> 5;                       // K = 32
    const int t  = threadIdx.x;
    const int w  = t >> 5;                        // warp 0..3
    const int j  = t & 31;                        // lane = float4 col

    // ---- init ----
    if (t <= NEWL) scnt[t] = 0;
    if (t < NEWL)  { stsum[t] = 0.f; smsum[t] = 0.f; }
    const float4 ninf = make_float4(NEG_INF, NEG_INF, NEG_INF, NEG_INF);
    #pragma unroll
    for (int i = t; i < 4 * CPY; i += 128) acc[i] = ninf;
    __syncthreads();

    // ---- seg / counts / tsum / msum from et & npm rows (L2-hot) ----
    #pragma unroll
    for (int l = t; l < Lq; l += 128) {
        float tv = __ldg(&et[b * Lq + l]);
        int   s  = seg_of(tv);
        sseg[l] = (unsigned char)s;
        atomicAdd(&scnt[s], 1);
        if (s < NEWL) {
            atomicAdd(&stsum[s], tv);
            float mv = __ldg(&npm[(size_t)bk * Lq + l]);
            if (mv != 0.f) atomicAdd(&smsum[s], mv);   // 0/1 values -> exact
        }
    }
    __syncthreads();

    // ---- main: sequential stream, warp w rows l = 4*i + w ----
    float4* myacc = acc + w * CPY;
    const float4* row4 = reinterpret_cast<const float4*>(h0 + (size_t)bk * Lq * Dq);
    for (int i0 = 0; i0 < 256; i0 += 8) {
        float4 v[8];
        int    ss[8];
        #pragma unroll
        for (int r = 0; r < 8; ++r) {             // stage: 8 independent LDG.128
            int l = ((i0 + r) << 2) + w;
            v[r]  = __ldcs(&row4[l * 32 + j]);
            ss[r] = sseg[l];
        }
        #pragma unroll
        for (int r = 0; r < 8; ++r) {             // smem RMW (private copy)
            float4* p = &myacc[ss[r] * 32 + j];
            float4 u = *p;
            u.x = fmaxf(u.x, v[r].x); u.y = fmaxf(u.y, v[r].y);
            u.z = fmaxf(u.z, v[r].z); u.w = fmaxf(u.w, v[r].w);
            *p = u;
        }
    }
    __syncthreads();

    // ---- merge 4 copies + include_zero + write (coalesced float4) ----
    #pragma unroll
    for (int sl = t; sl < NEWL * 32; sl += 128) { // sl = s*32 + j'
        float4 m0 = acc[sl],           m1 = acc[CPY + sl];
        float4 m2 = acc[2 * CPY + sl], m3 = acc[3 * CPY + sl];
        float4 m;
        m.x = fmaxf(fmaxf(m0.x, m1.x), fmaxf(m2.x, m3.x));
        m.y = fmaxf(fmaxf(m0.y, m1.y), fmaxf(m2.y, m3.y));
        m.z = fmaxf(fmaxf(m0.z, m1.z), fmaxf(m2.z, m3.z));
        m.w = fmaxf(fmaxf(m0.w, m1.w), fmaxf(m2.w, m3.w));
        int s = sl >> 5;
        if (scnt[s] < Lq) {                       // include_zero (empty: -inf -> 0)
            m.x = fmaxf(m.x, 0.f); m.y = fmaxf(m.y, 0.f);
            m.z = fmaxf(m.z, 0.f); m.w = fmaxf(m.w, 0.f);
        }
        reinterpret_cast<float4*>(o_h)[(size_t)bk * (NEWL * 32) + sl] = m;
    }
    if (t < NEWL) {
        float denom = fmaxf((float)scnt[t], 1.f);
        o_pm[bk * NEWL + t] = smsum[t] / denom;
        o_et[bk * NEWL + t] = stsum[t] / denom;
    }
}

extern "C" void kernel_launch(void* const* d_in, const int* in_sizes, int n_in,
                              void* d_out, int out_size) {
    const float* h0  = (const float*)d_in[0];
    const float* et  = (const float*)d_in[1];
    const float* npm = (const float*)d_in[2];
    float* out = (float*)d_out;

    float* o_h  = out;                              // (16,32,48,128) = 3,145,728
    float* o_et = out + 3145728;                    // (16,32,48)     =    24,576
    float* o_pm = out + 3145728 + 24576;            // (16,32,48)     =    24,576
    float* o_a  = out + 3145728 + 24576 + 24576;    // (16,32,1024,48)= 25,165,824

    static bool attr_set = false;
    if (!attr_set) {
        cudaFuncSetAttribute(segmax_stream,
                             cudaFuncAttributeMaxDynamicSharedMemorySize, DSMEM);
        attr_set = true;
    }

    almat_kernel<<<N_ALM, NTHR>>>(et, o_a);
    segmax_stream<<<Bq * Kq, 128, DSMEM>>>(h0, et, npm, o_h, o_pm, o_et);
}

// round 17
// speedup vs baseline: 1.6610x; 1.6610x over previous
#include <cuda_runtime.h>

#define Bq   16
#define Kq   32
#define Lq   1024
#define Dq   128
#define NEWL 48

// ---- scratch ----
__device__ int   g_order[Bq * Lq];          // l indices sorted by segment, STABLE
__device__ int   g_off[Bq * (NEWL + 1)];
__device__ float g_tsum[Bq * NEWL];

#define NEG_INF __int_as_float(0xff800000)
#define FMAX4(a, v) { a.x = fmaxf(a.x, v.x); a.y = fmaxf(a.y, v.y); \
                      a.z = fmaxf(a.z, v.z); a.w = fmaxf(a.w, v.w); }

#define NTHR   384
#define N_ALM  16384u      // almat blocks: 6,291,456 float4 / 384 (exact)
#define NCHK   8           // prep chunks of 128 elements

__device__ __forceinline__ int seg_of(float tv) {
    return (tv >= 0.f && tv < 48.f) ? (int)tv : NEWL;
}

// K0: STABLE chunked counting sort (16 blocks, ~3us).
__global__ void __launch_bounds__(NTHR) prep_kernel(const float* __restrict__ et) {
    const int t = threadIdx.x;
    const int b = blockIdx.x;
    __shared__ float sev[Lq];
    __shared__ int   cnt8[NCHK][NEWL + 1];
    __shared__ int   tots[NEWL + 1];
    __shared__ int   soff[NEWL + 1];
    __shared__ int   coff[NCHK][NEWL];
    __shared__ float ts[NEWL];

    for (int i = t; i < NCHK * (NEWL + 1); i += NTHR) ((int*)cnt8)[i] = 0;
    if (t < NEWL) ts[t] = 0.f;
    for (int i = t; i < Lq; i += NTHR) sev[i] = __ldg(&et[b * Lq + i]);
    __syncthreads();

    for (int l = t; l < Lq; l += NTHR) {
        float tv = sev[l];
        int   s  = seg_of(tv);
        atomicAdd(&cnt8[l >> 7][s], 1);
        if (s < NEWL) atomicAdd(&ts[s], tv);
    }
    __syncthreads();

    if (t <= NEWL) {
        int tot = 0;
        #pragma unroll
        for (int c = 0; c < NCHK; ++c) tot += cnt8[c][t];
        tots[t] = tot;
    }
    __syncthreads();
    if (t <= NEWL) {
        int a = 0;
        for (int i = 0; i < t; ++i) a += tots[i];
        soff[t] = a;
        g_off[b * (NEWL + 1) + t] = a;
        if (t < NEWL) g_tsum[b * NEWL + t] = ts[t];
    }
    __syncthreads();

    {   // per-(segment,chunk) starts: 48*8 = 384 threads exactly
        int s = t >> 3, c = t & 7;
        int a = soff[s];
        for (int cc = 0; cc < c; ++cc) a += cnt8[cc][s];
        coff[c][s] = a;
    }
    __syncthreads();

    {   // emit: thread (s,c) scans its 128-element chunk in ascending l
        int s = t >> 3, c = t & 7;
        int pos = coff[c][s];
        int l0 = c << 7;
        #pragma unroll 4
        for (int l = l0; l < l0 + 128; ++l)
            if (seg_of(sev[l]) == s) g_order[b * Lq + pos++] = l;
    }
}

// K1: almat (B,K,L,48) one-hot, float4 stores — runs on forked stream.
__global__ void __launch_bounds__(NTHR) almat_kernel(const float* __restrict__ et,
                                                     float* __restrict__ out_a) {
    unsigned g   = blockIdx.x * (unsigned)NTHR + threadIdx.x;   // exact cover
    unsigned row = g / 12u;
    unsigned qq  = g - row * 12u;
    unsigned l   = row & (Lq - 1);
    unsigned b   = row >> 15;             // / (K*L), K*L = 2^15
    float tv = __ldg(&et[b * Lq + l]);
    int s = seg_of(tv);
    float4 v = make_float4(0.f, 0.f, 0.f, 0.f);
    int o = s - (int)(qq * 4u);
    if (o >= 0 && o < 4) (&v.x)[o] = 1.f;
    reinterpret_cast<float4*>(out_a)[g] = v;
}

// K2: segmax + pad_mask + event_time (unchanged from R15 best).
__global__ void __launch_bounds__(256) segmax_kernel(const float* __restrict__ h0,
                                                     const float* __restrict__ npm,
                                                     float* __restrict__ o_h,
                                                     float* __restrict__ o_pm,
                                                     float* __restrict__ o_et) {
    const int bk = blockIdx.y;
    const int b  = bk >> 5;
    const int w  = threadIdx.x >> 5;
    const int j  = threadIdx.x & 31;
    const int s  = blockIdx.x * 8 + w;

    const int off = g_off[b * (NEWL + 1) + s];
    const int cnt = g_off[b * (NEWL + 1) + s + 1] - off;
    const int* idx = g_order + b * Lq + off;

    const float4* base4 = reinterpret_cast<const float4*>(h0 + (size_t)bk * Lq * Dq) + j;
    float4 a0 = make_float4(NEG_INF, NEG_INF, NEG_INF, NEG_INF);
    float4 a1 = a0, a2 = a0, a3 = a0;
    int i = 0;
    for (; i + 4 <= cnt; i += 4) {
        int l0 = idx[i];     int l1 = idx[i + 1];
        int l2 = idx[i + 2]; int l3 = idx[i + 3];
        float4 v0 = __ldcs(base4 + l0 * 32);
        float4 v1 = __ldcs(base4 + l1 * 32);
        float4 v2 = __ldcs(base4 + l2 * 32);
        float4 v3 = __ldcs(base4 + l3 * 32);
        FMAX4(a0, v0); FMAX4(a1, v1); FMAX4(a2, v2); FMAX4(a3, v3);
    }
    for (; i < cnt; ++i) {
        float4 v = __ldcs(base4 + idx[i] * 32);
        FMAX4(a0, v);
    }
    FMAX4(a0, a1); FMAX4(a2, a3); FMAX4(a0, a2);
    if (cnt < Lq) {
        float4 z = make_float4(0.f, 0.f, 0.f, 0.f);
        FMAX4(a0, z);
    }
    reinterpret_cast<float4*>(o_h)[((size_t)bk * NEWL + s) * 32 + j] = a0;

    const float* mrow = npm + (size_t)bk * Lq;
    float msum = 0.f;
    for (int i2 = j; i2 < cnt; i2 += 32) msum += __ldg(&mrow[idx[i2]]);
    #pragma unroll
    for (int d = 16; d > 0; d >>= 1) msum += __shfl_down_sync(0xffffffffu, msum, d);
    if (j == 0) {
        float denom = fmaxf((float)cnt, 1.f);
        o_pm[bk * NEWL + s] = msum / denom;
        o_et[bk * NEWL + s] = g_tsum[b * NEWL + s] / denom;
    }
}

extern "C" void kernel_launch(void* const* d_in, const int* in_sizes, int n_in,
                              void* d_out, int out_size) {
    const float* h0  = (const float*)d_in[0];
    const float* et  = (const float*)d_in[1];
    const float* npm = (const float*)d_in[2];
    float* out = (float*)d_out;

    float* o_h  = out;                              // (16,32,48,128) = 3,145,728
    float* o_et = out + 3145728;                    // (16,32,48)     =    24,576
    float* o_pm = out + 3145728 + 24576;            // (16,32,48)     =    24,576
    float* o_a  = out + 3145728 + 24576 + 24576;    // (16,32,1024,48)= 25,165,824

    // Lazily-created side stream + events (host resources only; created once).
    static cudaStream_t s2 = nullptr;
    static cudaEvent_t  evF = nullptr, evJ = nullptr;
    if (!s2) {
        cudaStreamCreateWithFlags(&s2, cudaStreamNonBlocking);
        cudaEventCreateWithFlags(&evF, cudaEventDisableTiming);
        cudaEventCreateWithFlags(&evJ, cudaEventDisableTiming);
    }

    // Fork: almat (independent) on s2, concurrent with prep -> segmax on main.
    cudaEventRecord(evF, 0);
    cudaStreamWaitEvent(s2, evF, 0);
    almat_kernel<<<N_ALM, NTHR, 0, s2>>>(et, o_a);

    prep_kernel<<<Bq, NTHR>>>(et);
    dim3 grid(6, Bq * Kq);
    segmax_kernel<<<grid, 256>>>(h0, npm, o_h, o_pm, o_et);

    // Join: main stream waits for almat before kernel_launch's work is "done".
    cudaEventRecord(evJ, s2);
    cudaStreamWaitEvent(0, evJ, 0);
}